// round 1
// baseline (speedup 1.0000x reference)
#include <cuda_runtime.h>
#include <float.h>
#include <math.h>

#define NROWS 8192
#define NCOLS 1000
#define NT 256

// Per-row scratch (deterministic, no atomics)
__device__ float g_ce[NROWS];
__device__ float g_a[NROWS];
__device__ float g_mx[NROWS];

__device__ __forceinline__ float2 top2_combine(float2 a, float2 b) {
    return (a.x >= b.x) ? make_float2(a.x, fmaxf(a.y, b.x))
                        : make_float2(b.x, fmaxf(b.y, a.x));
}

__device__ __forceinline__ float2 warp_sum2(float2 v) {
#pragma unroll
    for (int o = 16; o > 0; o >>= 1) {
        v.x += __shfl_xor_sync(0xffffffffu, v.x, o);
        v.y += __shfl_xor_sync(0xffffffffu, v.y, o);
    }
    return v;
}

__device__ __forceinline__ float2 warp_top2(float2 v) {
#pragma unroll
    for (int o = 16; o > 0; o >>= 1) {
        float2 w;
        w.x = __shfl_xor_sync(0xffffffffu, v.x, o);
        w.y = __shfl_xor_sync(0xffffffffu, v.y, o);
        v = top2_combine(v, w);
    }
    return v;
}

__device__ __forceinline__ float2 block_sum2(float2 v, float2* sp, float2* sb) {
    const int tid = threadIdx.x, w = tid >> 5, l = tid & 31;
    v = warp_sum2(v);
    if (l == 0) sp[w] = v;
    __syncthreads();
    if (w == 0) {
        float2 r = (l < (NT >> 5)) ? sp[l] : make_float2(0.f, 0.f);
        r = warp_sum2(r);
        if (l == 0) *sb = r;
    }
    __syncthreads();
    return *sb;
}

__device__ __forceinline__ float2 block_top2(float2 v, float2* sp, float2* sb) {
    const int tid = threadIdx.x, w = tid >> 5, l = tid & 31;
    v = warp_top2(v);
    if (l == 0) sp[w] = v;
    __syncthreads();
    if (w == 0) {
        float2 r = (l < (NT >> 5)) ? sp[l] : make_float2(-FLT_MAX, -FLT_MAX);
        r = warp_top2(r);
        if (l == 0) *sb = r;
    }
    __syncthreads();
    return *sb;
}

__global__ __launch_bounds__(NT)
void row_kernel(const float* __restrict__ t1, const float* __restrict__ t2,
                const float* __restrict__ t3, const float* __restrict__ t4,
                const float* __restrict__ t5, const float* __restrict__ os,
                const int* __restrict__ tg) {
    __shared__ float2 sp[NT >> 5];
    __shared__ float2 sb;
    __shared__ float  stgt[7];   // target logits: 5 teachers, mimic, out_s

    const int  row    = blockIdx.x;
    const int  tid    = threadIdx.x;
    const bool ok     = tid < (NCOLS / 4);   // 250 active lanes, 4 cols each
    const int  c0     = tid * 4;
    const long base   = (long)row * NCOLS;
    const int  target = tg[row];

    const float* tp[5] = {t1, t2, t3, t4, t5};
    float tv[5][4], mv[4], sv[4];

    // ---- Load: aligned float4 per tensor (row stride 4000B is 16B aligned) ----
#pragma unroll
    for (int j = 0; j < 5; j++) {
        float4 v;
        if (ok) v = __ldg((const float4*)(tp[j] + base) + tid);
        else    v = make_float4(-FLT_MAX, -FLT_MAX, -FLT_MAX, -FLT_MAX);
        tv[j][0] = v.x; tv[j][1] = v.y; tv[j][2] = v.z; tv[j][3] = v.w;
    }
    {
        float4 v;
        if (ok) v = __ldg((const float4*)(os + base) + tid);
        else    v = make_float4(-FLT_MAX, -FLT_MAX, -FLT_MAX, -FLT_MAX);
        sv[0] = v.x; sv[1] = v.y; sv[2] = v.z; sv[3] = v.w;
    }
#pragma unroll
    for (int k = 0; k < 4; k++) {
        float s = tv[0][k] + tv[1][k] + tv[2][k] + tv[3][k] + tv[4][k];
        mv[k] = ok ? s * 0.2f : -FLT_MAX;
    }

    // ---- Grab all 7 target-column logits once ----
    if (ok && target >= c0 && target < c0 + 4) {
#pragma unroll
        for (int k = 0; k < 4; k++) {
            if (c0 + k == target) {
#pragma unroll
                for (int j = 0; j < 5; j++) stgt[j] = tv[j][k];
                stgt[5] = mv[k];
                stgt[6] = sv[k];
            }
        }
    }
    __syncthreads();

    const float INV_T = 0.05f;   // 1 / T_KD
    const float T2    = 400.f;   // T_KD^2

    // ---- out_s: CE log-softmax + T_KD log-softmax ----
    float lm = fmaxf(fmaxf(sv[0], sv[1]), fmaxf(sv[2], sv[3]));
    float max_s = block_top2(make_float2(lm, -FLT_MAX), sp, &sb).x;

    float2 acc = make_float2(0.f, 0.f);
    if (ok) {
#pragma unroll
        for (int k = 0; k < 4; k++) {
            float d = sv[k] - max_s;
            acc.x += __expf(d);
            acc.y += __expf(d * INV_T);
        }
    }
    acc = block_sum2(acc, sp, &sb);
    const float CE   = max_s + __logf(acc.x) - stgt[6];
    const float lseT = __logf(acc.y);
    float lps[4];
#pragma unroll
    for (int k = 0; k < 4; k++) lps[k] = (sv[k] - max_s) * INV_T - lseT;

    // ---- Per-source (5 teachers + mimic): top2, margin, KD ----
    float margins[6], kd[6];
    float tmax = -FLT_MAX;
#pragma unroll
    for (int j = 0; j < 6; j++) {
        float2 lt = make_float2(-FLT_MAX, -FLT_MAX);
#pragma unroll
        for (int k = 0; k < 4; k++) {
            float x = (j < 5) ? tv[j][k] : mv[k];
            if (x > lt.x) { lt.y = lt.x; lt.x = x; }
            else if (x > lt.y) { lt.y = x; }
        }
        float2 m12 = block_top2(lt, sp, &sb);

        float2 a2 = make_float2(0.f, 0.f);
        if (ok) {
#pragma unroll
            for (int k = 0; k < 4; k++) {
                float x = (j < 5) ? tv[j][k] : mv[k];
                float e = __expf((x - m12.x) * INV_T);
                a2.x += e;
                a2.y += e * lps[k];
            }
        }
        a2 = block_sum2(a2, sp, &sb);

        kd[j]      = -T2 * (a2.y / a2.x);
        margins[j] = (stgt[j] == m12.x) ? (m12.x - m12.y) : 0.f;
        if (j < 5) tmax = fmaxf(tmax, m12.x);
    }

    // ---- Row combine: thr softmax over 6 sources; fold CE out ----
    if (tid == 0) {
        float mm = margins[0];
#pragma unroll
        for (int j = 1; j < 6; j++) mm = fmaxf(mm, margins[j]);
        float se = 0.f, A = 0.f;
#pragma unroll
        for (int j = 0; j < 6; j++) {
            float e = __expf((margins[j] - mm) * 0.5f);  // 1 / T_TH
            se += e;
            A  += e * stgt[j] * (kd[j] - CE);
        }
        g_ce[row] = CE;
        g_a[row]  = A / se;
        g_mx[row] = tmax;
    }
}

__global__ __launch_bounds__(1024)
void finalize_kernel(float* __restrict__ out) {
    __shared__ float s1[32], s2[32], s3[32];
    const int tid = threadIdx.x;
    float ce = 0.f, a = 0.f, mx = -FLT_MAX;
    for (int i = tid; i < NROWS; i += 1024) {
        ce += g_ce[i];
        a  += g_a[i];
        mx  = fmaxf(mx, g_mx[i]);
    }
#pragma unroll
    for (int o = 16; o > 0; o >>= 1) {
        ce += __shfl_xor_sync(0xffffffffu, ce, o);
        a  += __shfl_xor_sync(0xffffffffu, a, o);
        mx  = fmaxf(mx, __shfl_xor_sync(0xffffffffu, mx, o));
    }
    const int w = tid >> 5, l = tid & 31;
    if (l == 0) { s1[w] = ce; s2[w] = a; s3[w] = mx; }
    __syncthreads();
    if (w == 0) {
        ce = s1[l]; a = s2[l]; mx = s3[l];   // exactly 32 warps
#pragma unroll
        for (int o = 16; o > 0; o >>= 1) {
            ce += __shfl_xor_sync(0xffffffffu, ce, o);
            a  += __shfl_xor_sync(0xffffffffu, a, o);
            mx  = fmaxf(mx, __shfl_xor_sync(0xffffffffu, mx, o));
        }
        if (l == 0) {
            const float invB = 1.0f / (float)NROWS;
            out[0] = ce * invB + (0.8f / mx) * (a * invB);
        }
    }
}

extern "C" void kernel_launch(void* const* d_in, const int* in_sizes, int n_in,
                              void* d_out, int out_size) {
    const float* t1 = (const float*)d_in[0];
    const float* t2 = (const float*)d_in[1];
    const float* t3 = (const float*)d_in[2];
    const float* t4 = (const float*)d_in[3];
    const float* t5 = (const float*)d_in[4];
    const float* os = (const float*)d_in[5];
    const int*   tg = (const int*)d_in[6];

    row_kernel<<<NROWS, NT>>>(t1, t2, t3, t4, t5, os, tg);
    finalize_kernel<<<1, 1024>>>((float*)d_out);
}

// round 2
// speedup vs baseline: 1.5013x; 1.5013x over previous
#include <cuda_runtime.h>
#include <float.h>

#define NROWS 8192
#define NCOLS 1000
#define NT 256
#define NWARP (NT / 32)
#define NQ 26
// r[0..11]  : top2 pairs for 6 sources (max, second)
// r[12]     : sum e^{s}
// r[13]     : sum e^{s/T}
// r[14+j]   : S1_j = sum e^{x_j/T}
// r[20+j]   : S2_j = sum e^{x_j/T} * (s/T)

__device__ float g_ce[NROWS];
__device__ float g_a[NROWS];
__device__ float g_mx[NROWS];

__device__ __forceinline__ void combine26(float* r, const float* t) {
#pragma unroll
    for (int j = 0; j < 6; j++) {
        float bx = t[2 * j], by = t[2 * j + 1];
        if (bx > r[2 * j]) {
            float old = r[2 * j];
            r[2 * j] = bx;
            r[2 * j + 1] = fmaxf(by, old);
        } else {
            r[2 * j + 1] = fmaxf(r[2 * j + 1], bx);
        }
    }
#pragma unroll
    for (int i = 12; i < NQ; i++) r[i] += t[i];
}

__global__ __launch_bounds__(NT)
void row_kernel(const float* __restrict__ t1, const float* __restrict__ t2,
                const float* __restrict__ t3, const float* __restrict__ t4,
                const float* __restrict__ t5, const float* __restrict__ os,
                const int* __restrict__ tg) {
    __shared__ float sp[NWARP][NQ];
    __shared__ float stgt[7];

    const int  row    = blockIdx.x;
    const int  tid    = threadIdx.x;
    const bool ok     = tid < (NCOLS / 4);   // 250 active lanes, 4 cols each
    const long base   = (long)row * NCOLS;
    const int  target = __ldg(tg + row);

    const float INV_T   = 0.05f;   // 1/T_KD
    const float T2      = 400.f;   // T_KD^2
    const float INV_TTH = 0.5f;    // 1/T_TH

    float r[NQ];
#pragma unroll
    for (int i = 0; i < 12; i++) r[i] = -FLT_MAX;
#pragma unroll
    for (int i = 12; i < NQ; i++) r[i] = 0.f;

    if (ok) {
        // Front-batched aligned 128-bit loads (row stride 4000B is 16B aligned)
        float4 v0 = __ldg((const float4*)(t1 + base) + tid);
        float4 v1 = __ldg((const float4*)(t2 + base) + tid);
        float4 v2 = __ldg((const float4*)(t3 + base) + tid);
        float4 v3 = __ldg((const float4*)(t4 + base) + tid);
        float4 v4 = __ldg((const float4*)(t5 + base) + tid);
        float4 vs = __ldg((const float4*)(os + base) + tid);

        float a0[4] = {v0.x, v0.y, v0.z, v0.w};
        float a1[4] = {v1.x, v1.y, v1.z, v1.w};
        float a2[4] = {v2.x, v2.y, v2.z, v2.w};
        float a3[4] = {v3.x, v3.y, v3.z, v3.w};
        float a4[4] = {v4.x, v4.y, v4.z, v4.w};
        float as[4] = {vs.x, vs.y, vs.z, vs.w};

#pragma unroll
        for (int k = 0; k < 4; k++) {
            float m = (a0[k] + a1[k] + a2[k] + a3[k] + a4[k]) * 0.2f;
            float s = as[k];
            float x[6] = {a0[k], a1[k], a2[k], a3[k], a4[k], m};

            if (tid * 4 + k == target) {
#pragma unroll
                for (int j = 0; j < 6; j++) stgt[j] = x[j];
                stgt[6] = s;
            }

            r[12] += __expf(s);
            r[13] += __expf(s * INV_T);
            float lpw = s * INV_T;

#pragma unroll
            for (int j = 0; j < 6; j++) {
                float xv = x[j];
                if (xv > r[2 * j]) { r[2 * j + 1] = r[2 * j]; r[2 * j] = xv; }
                else if (xv > r[2 * j + 1]) { r[2 * j + 1] = xv; }
                float e = __expf(xv * INV_T);
                r[14 + j] += e;
                r[20 + j] = fmaf(e, lpw, r[20 + j]);
            }
        }
    }

    // ---- Single batched reduction: warp level ----
#pragma unroll
    for (int o = 16; o > 0; o >>= 1) {
        float t[NQ];
#pragma unroll
        for (int i = 0; i < NQ; i++) t[i] = __shfl_xor_sync(0xffffffffu, r[i], o);
        combine26(r, t);
    }
    const int w = tid >> 5, l = tid & 31;
    if (l == 0) {
#pragma unroll
        for (int i = 0; i < NQ; i++) sp[w][i] = r[i];
    }
    __syncthreads();   // the ONLY block barrier (also covers stgt writes)

    if (tid < NWARP) {
#pragma unroll
        for (int i = 0; i < NQ; i++) r[i] = sp[tid][i];
#pragma unroll
        for (int o = NWARP / 2; o > 0; o >>= 1) {
            float t[NQ];
#pragma unroll
            for (int i = 0; i < NQ; i++) t[i] = __shfl_xor_sync(0x000000ffu, r[i], o);
            combine26(r, t);
        }
        if (tid == 0) {
            float CE   = __logf(r[12]) - stgt[6];
            float lseT = __logf(r[13]);

            float tmax = r[0];
#pragma unroll
            for (int j = 1; j < 5; j++) tmax = fmaxf(tmax, r[2 * j]);

            float margins[6], kd[6];
#pragma unroll
            for (int j = 0; j < 6; j++) {
                kd[j]      = -T2 * (r[20 + j] / r[14 + j] - lseT);
                margins[j] = (stgt[j] == r[2 * j]) ? (r[2 * j] - r[2 * j + 1]) : 0.f;
            }
            float mm = margins[0];
#pragma unroll
            for (int j = 1; j < 6; j++) mm = fmaxf(mm, margins[j]);
            float se = 0.f, A = 0.f;
#pragma unroll
            for (int j = 0; j < 6; j++) {
                float e = __expf((margins[j] - mm) * INV_TTH);
                se += e;
                A  += e * stgt[j] * (kd[j] - CE);
            }
            g_ce[row] = CE;
            g_a[row]  = A / se;
            g_mx[row] = tmax;
        }
    }
}

__global__ __launch_bounds__(1024)
void finalize_kernel(float* __restrict__ out) {
    __shared__ float s1[32], s2[32], s3[32];
    const int tid = threadIdx.x;

    const float4* c4 = (const float4*)g_ce;
    const float4* a4 = (const float4*)g_a;
    const float4* m4 = (const float4*)g_mx;

    // 8192 floats = 2048 float4 per array; 1024 threads x 2 each, MLP=6
    float4 c0 = c4[tid], c1 = c4[tid + 1024];
    float4 aa0 = a4[tid], aa1 = a4[tid + 1024];
    float4 m0 = m4[tid], m1 = m4[tid + 1024];

    float ce = (c0.x + c0.y) + (c0.z + c0.w) + (c1.x + c1.y) + (c1.z + c1.w);
    float a  = (aa0.x + aa0.y) + (aa0.z + aa0.w) + (aa1.x + aa1.y) + (aa1.z + aa1.w);
    float mx = fmaxf(fmaxf(fmaxf(m0.x, m0.y), fmaxf(m0.z, m0.w)),
                     fmaxf(fmaxf(m1.x, m1.y), fmaxf(m1.z, m1.w)));

#pragma unroll
    for (int o = 16; o > 0; o >>= 1) {
        ce += __shfl_xor_sync(0xffffffffu, ce, o);
        a  += __shfl_xor_sync(0xffffffffu, a, o);
        mx  = fmaxf(mx, __shfl_xor_sync(0xffffffffu, mx, o));
    }
    const int w = tid >> 5, l = tid & 31;
    if (l == 0) { s1[w] = ce; s2[w] = a; s3[w] = mx; }
    __syncthreads();
    if (w == 0) {
        ce = s1[l]; a = s2[l]; mx = s3[l];   // exactly 32 warps
#pragma unroll
        for (int o = 16; o > 0; o >>= 1) {
            ce += __shfl_xor_sync(0xffffffffu, ce, o);
            a  += __shfl_xor_sync(0xffffffffu, a, o);
            mx  = fmaxf(mx, __shfl_xor_sync(0xffffffffu, mx, o));
        }
        if (l == 0) {
            const float invB = 1.0f / (float)NROWS;
            out[0] = ce * invB + (0.8f / mx) * (a * invB);
        }
    }
}

extern "C" void kernel_launch(void* const* d_in, const int* in_sizes, int n_in,
                              void* d_out, int out_size) {
    const float* t1 = (const float*)d_in[0];
    const float* t2 = (const float*)d_in[1];
    const float* t3 = (const float*)d_in[2];
    const float* t4 = (const float*)d_in[3];
    const float* t5 = (const float*)d_in[4];
    const float* os = (const float*)d_in[5];
    const int*   tg = (const int*)d_in[6];

    row_kernel<<<NROWS, NT>>>(t1, t2, t3, t4, t5, os, tg);
    finalize_kernel<<<1, 1024>>>((float*)d_out);
}